// round 3
// baseline (speedup 1.0000x reference)
#include <cuda_runtime.h>
#include <cuda_bf16.h>

// Shapes (known from reference): N=100000, E=3200000, F_IN=128, H=16, C=2
#define MAXN 100000
#define MAXE 3200000

// Scratch (static __device__ arrays: allocation-free per harness rules)
__device__ float  d_deg [MAXN];
__device__ float  d_dinv[MAXN];
__device__ float4 d_g1  [MAXN * 4];    // g1[i] = (x@W1)[i] * dinv[i], 16 f32/node
__device__ float4 d_acc1[MAXN * 4];    // init = g1[i] (self loop), then scatter-add
__device__ float2 d_g2  [MAXN];        // g2[i] = (h1@W2)[i] * dinv[i]
__device__ float2 d_acc2[MAXN];

// ---------------------------------------------------------------------------
// K1: deg init (self-loop contributes 1 to every node's degree)
__global__ void k_deg_init(int N) {
    int i = blockIdx.x * blockDim.x + threadIdx.x;
    if (i < N) d_deg[i] = 1.0f;
}

// K2: accumulate in-degree on dst (edge_index is int32: [2, E])
__global__ void k_deg(const int* __restrict__ dst, int E) {
    int e = blockIdx.x * blockDim.x + threadIdx.x;
    if (e >= E) return;
    atomicAdd(&d_deg[dst[e]], 1.0f);
}

// K3: dinv = rsqrt(deg)   (deg >= 1 always, due to self loops)
__global__ void k_dinv(int N) {
    int i = blockIdx.x * blockDim.x + threadIdx.x;
    if (i < N) d_dinv[i] = rsqrtf(d_deg[i]);
}

// K4: g1[i] = (x[i] @ W1) * dinv[i]; acc1[i] = g1[i]  (self-loop init)
// One thread per node, 16 accumulators, x via float4, W1 staged in smem.
__global__ void k_gemm1(const float* __restrict__ x,
                        const float* __restrict__ W1, int N) {
    __shared__ float4 W1s[128 * 4];  // W1[k][j] grouped as float4 over j
    for (int i = threadIdx.x; i < 512; i += blockDim.x)
        W1s[i] = ((const float4*)W1)[i];
    __syncthreads();

    int node = blockIdx.x * blockDim.x + threadIdx.x;
    if (node >= N) return;

    float acc[16];
#pragma unroll
    for (int j = 0; j < 16; j++) acc[j] = 0.0f;

    const float4* x4 = (const float4*)x + (size_t)node * 32;
#pragma unroll 4
    for (int k4 = 0; k4 < 32; k4++) {
        float4 xv = __ldg(&x4[k4]);
#pragma unroll
        for (int kk = 0; kk < 4; kk++) {
            float xs = (kk == 0) ? xv.x : (kk == 1) ? xv.y : (kk == 2) ? xv.z : xv.w;
            int k = k4 * 4 + kk;
#pragma unroll
            for (int j4 = 0; j4 < 4; j4++) {
                float4 w = W1s[k * 4 + j4];
                acc[j4 * 4 + 0] += xs * w.x;
                acc[j4 * 4 + 1] += xs * w.y;
                acc[j4 * 4 + 2] += xs * w.z;
                acc[j4 * 4 + 3] += xs * w.w;
            }
        }
    }

    float dv = d_dinv[node];
#pragma unroll
    for (int j4 = 0; j4 < 4; j4++) {
        float4 g = make_float4(acc[j4 * 4 + 0] * dv, acc[j4 * 4 + 1] * dv,
                               acc[j4 * 4 + 2] * dv, acc[j4 * 4 + 3] * dv);
        d_g1[node * 4 + j4]   = g;
        d_acc1[node * 4 + j4] = g;
    }
}

// K5: scatter layer 1 — 4 lanes per edge, each moves one float4 (4 scalar REDs)
__global__ void k_scatter1(const int* __restrict__ src,
                           const int* __restrict__ dst, int E) {
    int t = blockIdx.x * blockDim.x + threadIdx.x;
    int e = t >> 2;
    if (e >= E) return;
    int part = t & 3;
    int s = src[e];
    int d = dst[e];
    float4 g = d_g1[s * 4 + part];
    float* p = (float*)&d_acc1[d * 4 + part];
    atomicAdd(p + 0, g.x);
    atomicAdd(p + 1, g.y);
    atomicAdd(p + 2, g.z);
    atomicAdd(p + 3, g.w);
}

// K6: h1 = relu(dinv*acc1 + b1); g2 = (h1 @ W2) * dinv; acc2 = g2
__global__ void k_layer2_gemm(const float* __restrict__ b1,
                              const float* __restrict__ W2, int N) {
    int i = blockIdx.x * blockDim.x + threadIdx.x;
    if (i >= N) return;
    float dv = d_dinv[i];
    float o0 = 0.0f, o1 = 0.0f;
#pragma unroll
    for (int j4 = 0; j4 < 4; j4++) {
        float4 a = d_acc1[i * 4 + j4];
#pragma unroll
        for (int kk = 0; kk < 4; kk++) {
            int j = j4 * 4 + kk;
            float av = (kk == 0) ? a.x : (kk == 1) ? a.y : (kk == 2) ? a.z : a.w;
            float h = fmaxf(av * dv + __ldg(&b1[j]), 0.0f);
            o0 += h * __ldg(&W2[j * 2 + 0]);
            o1 += h * __ldg(&W2[j * 2 + 1]);
        }
    }
    float2 g = make_float2(o0 * dv, o1 * dv);
    d_g2[i]   = g;
    d_acc2[i] = g;
}

// K7: scatter layer 2 — one thread per edge, 2 scalar atomicAdds
__global__ void k_scatter2(const int* __restrict__ src,
                           const int* __restrict__ dst, int E) {
    int e = blockIdx.x * blockDim.x + threadIdx.x;
    if (e >= E) return;
    float2 g = d_g2[src[e]];
    float* p = (float*)&d_acc2[dst[e]];
    atomicAdd(p + 0, g.x);
    atomicAdd(p + 1, g.y);
}

// K8: out[i] = dinv[i]*acc2[i] + b2
__global__ void k_final(const float* __restrict__ b2, float* __restrict__ out,
                        int N) {
    int i = blockIdx.x * blockDim.x + threadIdx.x;
    if (i >= N) return;
    float dv = d_dinv[i];
    float2 a = d_acc2[i];
    float2 r = make_float2(a.x * dv + __ldg(&b2[0]), a.y * dv + __ldg(&b2[1]));
    ((float2*)out)[i] = r;
}

extern "C" void kernel_launch(void* const* d_in, const int* in_sizes, int n_in,
                              void* d_out, int out_size) {
    const float* x  = (const float*)d_in[0];
    const int*   ei = (const int*)d_in[1];   // int32 [2, E] (JAX x64 disabled)
    const float* W1 = (const float*)d_in[2];
    const float* b1 = (const float*)d_in[3];
    const float* W2 = (const float*)d_in[4];
    const float* b2 = (const float*)d_in[5];

    int N = in_sizes[0] / 128;
    int E = in_sizes[1] / 2;
    const int* src = ei;
    const int* dst = ei + E;

    k_deg_init<<<(N + 255) / 256, 256>>>(N);
    k_deg<<<(E + 255) / 256, 256>>>(dst, E);
    k_dinv<<<(N + 255) / 256, 256>>>(N);
    k_gemm1<<<(N + 127) / 128, 128>>>(x, W1, N);
    {
        long long t = 4LL * E;
        k_scatter1<<<(int)((t + 255) / 256), 256>>>(src, dst, E);
    }
    k_layer2_gemm<<<(N + 255) / 256, 256>>>(b1, W2, N);
    k_scatter2<<<(E + 255) / 256, 256>>>(src, dst, E);
    k_final<<<(N + 255) / 256, 256>>>(b2, (float*)d_out, N);
}